// round 1
// baseline (speedup 1.0000x reference)
#include <cuda_runtime.h>
#include <math.h>

#define N_NODES 100000
#define N_EDGES 1600000
#define DIN 64
#define DH 64
#define DOUT 16

// Scratch (allocation-free rule: __device__ globals)
__device__ __align__(16) float g_deg[N_NODES];
__device__ __align__(16) float g_agg1[N_NODES * DIN];        // sum_{src} x[src] per dst
__device__ __align__(16) float g_h1[N_NODES * DH];           // relu(layer1)
__device__ __align__(16) float g_pq[N_NODES * 32];           // per node: [p2(16) | q2(16)]
__device__ __align__(16) float g_agg2[N_NODES * DOUT];       // sum_{src} p2[src] per dst

// ---------------------------------------------------------------------------
// Zero scratch that is accumulated into
// ---------------------------------------------------------------------------
__global__ void zero_kernel() {
    int i = blockIdx.x * blockDim.x + threadIdx.x;
    int stride = gridDim.x * blockDim.x;
    float4 z = make_float4(0.f, 0.f, 0.f, 0.f);
    for (int t = i; t < N_NODES / 4; t += stride) ((float4*)g_deg)[t] = z;
    for (int t = i; t < N_NODES * DIN / 4; t += stride) ((float4*)g_agg1)[t] = z;
    for (int t = i; t < N_NODES * DOUT / 4; t += stride) ((float4*)g_agg2)[t] = z;
}

// ---------------------------------------------------------------------------
// Layer-1 edge aggregation: agg1[dst] += x[src]; deg[dst] += 1
// 16 threads per edge, one float4 per thread (RED.128)
// ---------------------------------------------------------------------------
__global__ void edge1_kernel(const int* __restrict__ ei, const float* __restrict__ x) {
    long long g = (long long)blockIdx.x * blockDim.x + threadIdx.x;
    int e = (int)(g >> 4);
    int c = (int)(g & 15);
    if (e >= N_EDGES) return;
    int src = __ldg(ei + e);
    int dst = __ldg(ei + N_EDGES + e);
    float4 v = __ldg((const float4*)x + src * 16 + c);
    atomicAdd((float4*)(g_agg1 + dst * 64 + c * 4), v);
    if (c == 0) atomicAdd(g_deg + dst, 1.0f);
}

// ---------------------------------------------------------------------------
// Layer 1: h1 = relu( (agg1*invdeg) @ W1l + x @ W1r + b1 )
// block = 256 threads, 64 nodes/block; thread: 2 nodes x 8 output cols
// ---------------------------------------------------------------------------
__global__ void __launch_bounds__(256) layer1_kernel(
    const float* __restrict__ x,
    const float* __restrict__ W1l,
    const float* __restrict__ W1r,
    const float* __restrict__ b1)
{
    __shared__ float sWl[64 * 64];
    __shared__ float sWr[64 * 64];
    int tid = threadIdx.x;
    for (int i = tid; i < 64 * 64 / 4; i += 256) {
        ((float4*)sWl)[i] = ((const float4*)W1l)[i];
        ((float4*)sWr)[i] = ((const float4*)W1r)[i];
    }
    __syncthreads();

    int js = tid & 7;          // 8 column slots of 8 cols
    int ns = tid >> 3;         // 32 node slots of 2 nodes
    int jb = js * 8;
    int n0 = blockIdx.x * 64 + ns * 2;
    int n1 = n0 + 1;
    bool v0 = n0 < N_NODES;
    bool v1 = n1 < N_NODES;

    float invd0 = v0 ? (1.f / fmaxf(g_deg[n0], 1.f)) : 0.f;
    float invd1 = v1 ? (1.f / fmaxf(g_deg[n1], 1.f)) : 0.f;

    const float4* x4 = (const float4*)x;
    const float4* a4 = (const float4*)g_agg1;
    float4 z4 = make_float4(0.f, 0.f, 0.f, 0.f);

    float acc0[8], acc1[8];
#pragma unroll
    for (int j = 0; j < 8; j++) { acc0[j] = 0.f; acc1[j] = 0.f; }

    for (int k4 = 0; k4 < 16; k4++) {
        float av0[4], av1[4], xv0[4], xv1[4];
        {
            float4 t;
            t = v0 ? a4[n0 * 16 + k4] : z4;
            av0[0] = t.x * invd0; av0[1] = t.y * invd0; av0[2] = t.z * invd0; av0[3] = t.w * invd0;
            t = v1 ? a4[n1 * 16 + k4] : z4;
            av1[0] = t.x * invd1; av1[1] = t.y * invd1; av1[2] = t.z * invd1; av1[3] = t.w * invd1;
            t = v0 ? x4[n0 * 16 + k4] : z4;
            xv0[0] = t.x; xv0[1] = t.y; xv0[2] = t.z; xv0[3] = t.w;
            t = v1 ? x4[n1 * 16 + k4] : z4;
            xv1[0] = t.x; xv1[1] = t.y; xv1[2] = t.z; xv1[3] = t.w;
        }
#pragma unroll
        for (int kk = 0; kk < 4; kk++) {
            int k = k4 * 4 + kk;
            float wl[8], wr[8];
            *(float4*)(wl)     = *(const float4*)(sWl + k * 64 + jb);
            *(float4*)(wl + 4) = *(const float4*)(sWl + k * 64 + jb + 4);
            *(float4*)(wr)     = *(const float4*)(sWr + k * 64 + jb);
            *(float4*)(wr + 4) = *(const float4*)(sWr + k * 64 + jb + 4);
#pragma unroll
            for (int jj = 0; jj < 8; jj++) {
                acc0[jj] += av0[kk] * wl[jj] + xv0[kk] * wr[jj];
                acc1[jj] += av1[kk] * wl[jj] + xv1[kk] * wr[jj];
            }
        }
    }

    float bv[8];
    *(float4*)(bv)     = *(const float4*)(b1 + jb);
    *(float4*)(bv + 4) = *(const float4*)(b1 + jb + 4);

    float o0[8], o1[8];
#pragma unroll
    for (int jj = 0; jj < 8; jj++) {
        o0[jj] = fmaxf(acc0[jj] + bv[jj], 0.f);
        o1[jj] = fmaxf(acc1[jj] + bv[jj], 0.f);
    }
    if (v0) {
        *(float4*)(g_h1 + n0 * 64 + jb)     = *(float4*)(o0);
        *(float4*)(g_h1 + n0 * 64 + jb + 4) = *(float4*)(o0 + 4);
    }
    if (v1) {
        *(float4*)(g_h1 + n1 * 64 + jb)     = *(float4*)(o1);
        *(float4*)(g_h1 + n1 * 64 + jb + 4) = *(float4*)(o1 + 4);
    }
}

// ---------------------------------------------------------------------------
// Layer-2 projections (done BEFORE aggregation since aggregation is linear):
//   p2 = h1 @ W2l            (to be mean-aggregated over edges)
//   q2 = h1 @ W2r + b2       (self term)
// stored interleaved: g_pq[n*32 + 0..15] = p2, [16..31] = q2
// block = 256 threads, 256 nodes/block; thread: 4 nodes x 8 cols (of 32)
// ---------------------------------------------------------------------------
__global__ void __launch_bounds__(256) proj2_kernel(
    const float* __restrict__ W2l,
    const float* __restrict__ W2r,
    const float* __restrict__ b2)
{
    __shared__ float sW[64 * 32];   // sW[k*32 + j]: j<16 -> W2l[k][j], else W2r[k][j-16]
    __shared__ float sb[32];
    int tid = threadIdx.x;
    for (int i = tid; i < 64 * 16; i += 256) {
        int k = i >> 4, j = i & 15;
        sW[k * 32 + j]      = W2l[i];
        sW[k * 32 + 16 + j] = W2r[i];
    }
    if (tid < 16) { sb[tid] = 0.f; sb[16 + tid] = b2[tid]; }
    __syncthreads();

    int cs = tid & 3;          // 4 col slots of 8
    int ns = tid >> 2;         // 64 node slots of 4
    int cb = cs * 8;
    int nbase = blockIdx.x * 256 + ns * 4;

    float acc[4][8];
#pragma unroll
    for (int n = 0; n < 4; n++)
#pragma unroll
        for (int j = 0; j < 8; j++) acc[n][j] = 0.f;

    const float4* h4 = (const float4*)g_h1;
    float4 z4 = make_float4(0.f, 0.f, 0.f, 0.f);

    for (int k4 = 0; k4 < 16; k4++) {
        float hv[4][4];
#pragma unroll
        for (int n = 0; n < 4; n++) {
            int node = nbase + n;
            float4 t = (node < N_NODES) ? h4[node * 16 + k4] : z4;
            hv[n][0] = t.x; hv[n][1] = t.y; hv[n][2] = t.z; hv[n][3] = t.w;
        }
#pragma unroll
        for (int kk = 0; kk < 4; kk++) {
            int k = k4 * 4 + kk;
            float wv[8];
            *(float4*)(wv)     = *(const float4*)(sW + k * 32 + cb);
            *(float4*)(wv + 4) = *(const float4*)(sW + k * 32 + cb + 4);
#pragma unroll
            for (int jj = 0; jj < 8; jj++) {
#pragma unroll
                for (int n = 0; n < 4; n++) acc[n][jj] += hv[n][kk] * wv[jj];
            }
        }
    }

    float bv[8];
    *(float4*)(bv)     = *(const float4*)(sb + cb);
    *(float4*)(bv + 4) = *(const float4*)(sb + cb + 4);

#pragma unroll
    for (int n = 0; n < 4; n++) {
        int node = nbase + n;
        if (node < N_NODES) {
            float o[8];
#pragma unroll
            for (int jj = 0; jj < 8; jj++) o[jj] = acc[n][jj] + bv[jj];
            *(float4*)(g_pq + node * 32 + cb)     = *(float4*)(o);
            *(float4*)(g_pq + node * 32 + cb + 4) = *(float4*)(o + 4);
        }
    }
}

// ---------------------------------------------------------------------------
// Layer-2 edge aggregation over projected features (16 floats/edge):
//   agg2[dst] += p2[src]
// 4 threads per edge, one float4 per thread
// ---------------------------------------------------------------------------
__global__ void edge2_kernel(const int* __restrict__ ei) {
    long long g = (long long)blockIdx.x * blockDim.x + threadIdx.x;
    int e = (int)(g >> 2);
    int c = (int)(g & 3);
    if (e >= N_EDGES) return;
    int src = __ldg(ei + e);
    int dst = __ldg(ei + N_EDGES + e);
    float4 v = __ldg((const float4*)g_pq + src * 8 + c);   // p2 = first 16 floats
    atomicAdd((float4*)(g_agg2 + dst * 16 + c * 4), v);
}

// ---------------------------------------------------------------------------
// Final: out = log_softmax( agg2*invdeg + q2 )
// ---------------------------------------------------------------------------
__global__ void final_kernel(float* __restrict__ out) {
    int n = blockIdx.x * blockDim.x + threadIdx.x;
    if (n >= N_NODES) return;
    float invd = 1.f / fmaxf(g_deg[n], 1.f);
    float v[16];
    const float4* a4 = (const float4*)g_agg2;
    const float4* q4 = (const float4*)g_pq;
#pragma unroll
    for (int c = 0; c < 4; c++) {
        float4 a = a4[n * 4 + c];
        float4 q = q4[n * 8 + 4 + c];    // q2 = floats 16..31 of the row
        v[c * 4 + 0] = a.x * invd + q.x;
        v[c * 4 + 1] = a.y * invd + q.y;
        v[c * 4 + 2] = a.z * invd + q.z;
        v[c * 4 + 3] = a.w * invd + q.w;
    }
    float m = v[0];
#pragma unroll
    for (int j = 1; j < 16; j++) m = fmaxf(m, v[j]);
    float s = 0.f;
#pragma unroll
    for (int j = 0; j < 16; j++) s += expf(v[j] - m);
    float lse = m + logf(s);
#pragma unroll
    for (int c = 0; c < 4; c++) {
        float4 o;
        o.x = v[c * 4 + 0] - lse;
        o.y = v[c * 4 + 1] - lse;
        o.z = v[c * 4 + 2] - lse;
        o.w = v[c * 4 + 3] - lse;
        ((float4*)out)[n * 4 + c] = o;
    }
}

// ---------------------------------------------------------------------------
extern "C" void kernel_launch(void* const* d_in, const int* in_sizes, int n_in,
                              void* d_out, int out_size) {
    const float* x   = (const float*)d_in[0];
    const int*   ei  = (const int*)d_in[1];
    const float* W1l = (const float*)d_in[2];
    const float* W1r = (const float*)d_in[3];
    const float* b1  = (const float*)d_in[4];
    const float* W2l = (const float*)d_in[5];
    const float* W2r = (const float*)d_in[6];
    const float* b2  = (const float*)d_in[7];
    float* out = (float*)d_out;

    zero_kernel<<<2048, 256>>>();

    {   // 16 threads / edge
        long long total = (long long)N_EDGES * 16;
        int blocks = (int)((total + 255) / 256);
        edge1_kernel<<<blocks, 256>>>(ei, x);
    }

    layer1_kernel<<<(N_NODES + 63) / 64, 256>>>(x, W1l, W1r, b1);

    proj2_kernel<<<(N_NODES + 255) / 256, 256>>>(W2l, W2r, b2);

    {   // 4 threads / edge
        long long total = (long long)N_EDGES * 4;
        int blocks = (int)((total + 255) / 256);
        edge2_kernel<<<blocks, 256>>>(ei);
    }

    final_kernel<<<(N_NODES + 255) / 256, 256>>>(out);
}

// round 2
// speedup vs baseline: 1.7696x; 1.7696x over previous
#include <cuda_runtime.h>
#include <math.h>

#define NN 100000
#define NE 1600000

// ---------------- scratch (__device__ globals; no allocation) ----------------
__device__ __align__(16) int   g_rowptr[NN + 1];
__device__ __align__(16) int   g_cursor[NN];      // also used as histogram counts
__device__ __align__(16) int   g_blocksum[256];
__device__ __align__(16) int   g_blockoff[256];
__device__ __align__(16) int   g_csr[NE];         // src indices bucketed by dst
__device__ __align__(16) float g_pq[NN * 32];     // per node: [p2(16) | q2(16)]

// ---------------------------------------------------------------------------
// CSR build: zero counts -> histogram -> scan (3 phases) -> fill buckets
// ---------------------------------------------------------------------------
__global__ void k_zero_cnt() {
    int g = blockIdx.x * blockDim.x + threadIdx.x;
    if (g < NN) g_cursor[g] = 0;
}

__global__ void k_hist(const int* __restrict__ ei) {
    int e = blockIdx.x * blockDim.x + threadIdx.x;
    if (e < NE) atomicAdd(&g_cursor[__ldg(ei + NE + e)], 1);
}

__device__ __forceinline__ int warp_incl_scan(int v) {
    int lane = threadIdx.x & 31;
#pragma unroll
    for (int d = 1; d < 32; d <<= 1) {
        int t = __shfl_up_sync(0xFFFFFFFFu, v, d);
        if (lane >= d) v += t;
    }
    return v;
}

// 512 threads/block, 196 blocks: local exclusive scan + per-block total
__global__ void __launch_bounds__(512) k_scan1() {
    __shared__ int ws[16];
    int tid = threadIdx.x;
    int g = blockIdx.x * 512 + tid;
    int v = (g < NN) ? g_cursor[g] : 0;
    int inc = warp_incl_scan(v);
    int wid = tid >> 5, lane = tid & 31;
    if (lane == 31) ws[wid] = inc;
    __syncthreads();
    if (wid == 0) {
        int t = (lane < 16) ? ws[lane] : 0;
        t = warp_incl_scan(t);
        if (lane < 16) ws[lane] = t;
    }
    __syncthreads();
    int off = (wid > 0) ? ws[wid - 1] : 0;
    int excl = inc - v + off;
    if (g < NN) g_rowptr[g] = excl;
    if (tid == 511) g_blocksum[blockIdx.x] = excl + v;  // block total
}

// single block: exclusive scan of 196 block sums
__global__ void __launch_bounds__(256) k_scan2() {
    __shared__ int ws[8];
    int tid = threadIdx.x;
    int v = (tid < 196) ? g_blocksum[tid] : 0;
    int inc = warp_incl_scan(v);
    int wid = tid >> 5, lane = tid & 31;
    if (lane == 31) ws[wid] = inc;
    __syncthreads();
    if (wid == 0) {
        int t = (lane < 8) ? ws[lane] : 0;
        t = warp_incl_scan(t);
        if (lane < 8) ws[lane] = t;
    }
    __syncthreads();
    int off = (wid > 0) ? ws[wid - 1] : 0;
    if (tid < 196) g_blockoff[tid] = inc - v + off;
}

__global__ void k_scan3() {
    int g = blockIdx.x * blockDim.x + threadIdx.x;
    if (g < NN) {
        int r = g_rowptr[g] + g_blockoff[g >> 9];
        g_rowptr[g] = r;
        g_cursor[g] = r;
    }
    if (g == 0) g_rowptr[NN] = NE;
}

__global__ void k_fill(const int* __restrict__ ei) {
    int e = blockIdx.x * blockDim.x + threadIdx.x;
    if (e < NE) {
        int src = __ldg(ei + e);
        int dst = __ldg(ei + NE + e);
        int pos = atomicAdd(&g_cursor[dst], 1);
        g_csr[pos] = src;
    }
}

// ---------------------------------------------------------------------------
// Mega kernel: gather mean(x) -> layer1 (relu) -> layer2 projections p2,q2
// 256 threads, 64 nodes / block.
// dyn smem: sWl[4096] sWr[4096] sW2[2048] sH[64*68] sB[32] sB1[64]
// ---------------------------------------------------------------------------
#define SH_STRIDE 68
#define SMEM_FLOATS (4096 + 4096 + 2048 + 64 * SH_STRIDE + 32 + 64)

__global__ void __launch_bounds__(256) mega_kernel(
    const float* __restrict__ x,
    const float* __restrict__ W1l, const float* __restrict__ W1r,
    const float* __restrict__ b1,
    const float* __restrict__ W2l, const float* __restrict__ W2r,
    const float* __restrict__ b2)
{
    extern __shared__ float smem[];
    float* sWl = smem;
    float* sWr = sWl + 4096;
    float* sW2 = sWr + 4096;
    float* sH  = sW2 + 2048;            // 64 x 68 (mean, later h1)
    float* sB  = sH + 64 * SH_STRIDE;   // 32: [0]*16 | b2
    float* sB1 = sB + 32;               // 64

    int tid = threadIdx.x;

    // weights -> smem
    for (int i = tid; i < 1024; i += 256) {
        ((float4*)sWl)[i] = ((const float4*)W1l)[i];
        ((float4*)sWr)[i] = ((const float4*)W1r)[i];
    }
    for (int i = tid; i < 64 * 16; i += 256) {
        int k = i >> 4, j = i & 15;
        sW2[k * 32 + j]      = W2l[i];
        sW2[k * 32 + 16 + j] = W2r[i];
    }
    if (tid < 16) { sB[tid] = 0.f; sB[16 + tid] = b2[tid]; }
    if (tid < 64) sB1[tid] = b1[tid];

    // ---- gather phase: mean of x over in-neighbors, 4 threads/node ----
    {
        int nl = tid >> 2;                 // local node 0..63
        int c  = tid & 3;                  // float4 lane within row-quarter
        int node = blockIdx.x * 64 + nl;
        int s = 0, e = 0;
        if (node < NN) { s = __ldg(g_rowptr + node); e = __ldg(g_rowptr + node + 1); }
        float4 acc[4];
#pragma unroll
        for (int j = 0; j < 4; j++) acc[j] = make_float4(0.f, 0.f, 0.f, 0.f);
        const float4* x4 = (const float4*)x;
        for (int i = s; i < e; i++) {
            int src = __ldg(g_csr + i);
            const float4* row = x4 + (size_t)src * 16 + c;
#pragma unroll
            for (int j = 0; j < 4; j++) {
                float4 v = __ldg(row + j * 4);
                acc[j].x += v.x; acc[j].y += v.y; acc[j].z += v.z; acc[j].w += v.w;
            }
        }
        float invd = 1.f / fmaxf((float)(e - s), 1.f);
        float4* dstp = (float4*)(sH + nl * SH_STRIDE);
#pragma unroll
        for (int j = 0; j < 4; j++) {
            float4 o;
            o.x = acc[j].x * invd; o.y = acc[j].y * invd;
            o.z = acc[j].z * invd; o.w = acc[j].w * invd;
            dstp[j * 4 + c] = o;
        }
    }
    __syncthreads();

    // ---- phase A: h1 = relu(mean @ W1l + x @ W1r + b1); 2 nodes x 8 cols ----
    int js = tid & 7, ns = tid >> 3;
    int jb = js * 8;
    int l0 = ns * 2, l1 = l0 + 1;
    int n0 = blockIdx.x * 64 + l0, n1 = n0 + 1;
    bool v0 = n0 < NN, v1 = n1 < NN;
    const float4* x4 = (const float4*)x;
    float4 z4 = make_float4(0.f, 0.f, 0.f, 0.f);

    float acc0[8], acc1[8];
#pragma unroll
    for (int j = 0; j < 8; j++) { acc0[j] = 0.f; acc1[j] = 0.f; }

    for (int k4 = 0; k4 < 16; k4++) {
        float4 a0 = *(float4*)(sH + l0 * SH_STRIDE + k4 * 4);
        float4 a1 = *(float4*)(sH + l1 * SH_STRIDE + k4 * 4);
        float4 X0 = v0 ? __ldg(x4 + (size_t)n0 * 16 + k4) : z4;
        float4 X1 = v1 ? __ldg(x4 + (size_t)n1 * 16 + k4) : z4;
        float av0[4] = {a0.x, a0.y, a0.z, a0.w};
        float av1[4] = {a1.x, a1.y, a1.z, a1.w};
        float xv0[4] = {X0.x, X0.y, X0.z, X0.w};
        float xv1[4] = {X1.x, X1.y, X1.z, X1.w};
#pragma unroll
        for (int kk = 0; kk < 4; kk++) {
            int k = k4 * 4 + kk;
            float wl[8], wr[8];
            *(float4*)(wl)     = *(const float4*)(sWl + k * 64 + jb);
            *(float4*)(wl + 4) = *(const float4*)(sWl + k * 64 + jb + 4);
            *(float4*)(wr)     = *(const float4*)(sWr + k * 64 + jb);
            *(float4*)(wr + 4) = *(const float4*)(sWr + k * 64 + jb + 4);
#pragma unroll
            for (int jj = 0; jj < 8; jj++) {
                acc0[jj] += av0[kk] * wl[jj] + xv0[kk] * wr[jj];
                acc1[jj] += av1[kk] * wl[jj] + xv1[kk] * wr[jj];
            }
        }
    }

    float o0[8], o1[8];
#pragma unroll
    for (int jj = 0; jj < 8; jj++) {
        o0[jj] = fmaxf(acc0[jj] + sB1[jb + jj], 0.f);
        o1[jj] = fmaxf(acc1[jj] + sB1[jb + jj], 0.f);
    }
    __syncthreads();   // everyone done reading mean from sH
    *(float4*)(sH + l0 * SH_STRIDE + jb)     = *(float4*)(o0);
    *(float4*)(sH + l0 * SH_STRIDE + jb + 4) = *(float4*)(o0 + 4);
    *(float4*)(sH + l1 * SH_STRIDE + jb)     = *(float4*)(o1);
    *(float4*)(sH + l1 * SH_STRIDE + jb + 4) = *(float4*)(o1 + 4);
    __syncthreads();

    // ---- phase B: [p2|q2] = h1 @ [W2l|W2r] + [0|b2]; 1 node x 8 cols ----
    {
        int nl = tid >> 2;
        int cs = tid & 3;
        int cb = cs * 8;
        int node = blockIdx.x * 64 + nl;
        float accB[8];
#pragma unroll
        for (int j = 0; j < 8; j++) accB[j] = 0.f;
        for (int k4 = 0; k4 < 16; k4++) {
            float4 h4 = *(float4*)(sH + nl * SH_STRIDE + k4 * 4);
            float hv[4] = {h4.x, h4.y, h4.z, h4.w};
#pragma unroll
            for (int kk = 0; kk < 4; kk++) {
                int k = k4 * 4 + kk;
                float wv[8];
                *(float4*)(wv)     = *(const float4*)(sW2 + k * 32 + cb);
                *(float4*)(wv + 4) = *(const float4*)(sW2 + k * 32 + cb + 4);
#pragma unroll
                for (int jj = 0; jj < 8; jj++) accB[jj] += hv[kk] * wv[jj];
            }
        }
        if (node < NN) {
            float o[8];
#pragma unroll
            for (int jj = 0; jj < 8; jj++) o[jj] = accB[jj] + sB[cb + jj];
            *(float4*)(g_pq + (size_t)node * 32 + cb)     = *(float4*)(o);
            *(float4*)(g_pq + (size_t)node * 32 + cb + 4) = *(float4*)(o + 4);
        }
    }
}

// ---------------------------------------------------------------------------
// Final: gather mean(p2) + q2 -> log_softmax -> out. 4 threads/node.
// ---------------------------------------------------------------------------
__global__ void __launch_bounds__(256) final_kernel(float* __restrict__ out) {
    int tid = threadIdx.x;
    int node = blockIdx.x * 64 + (tid >> 2);
    int c = tid & 3;
    bool nv = node < NN;
    int s = 0, e = 0;
    if (nv) { s = __ldg(g_rowptr + node); e = __ldg(g_rowptr + node + 1); }
    float4 acc = make_float4(0.f, 0.f, 0.f, 0.f);
    const float4* pq4 = (const float4*)g_pq;
    for (int i = s; i < e; i++) {
        int src = __ldg(g_csr + i);
        float4 v = __ldg(pq4 + (size_t)src * 8 + c);
        acc.x += v.x; acc.y += v.y; acc.z += v.z; acc.w += v.w;
    }
    float invd = 1.f / fmaxf((float)(e - s), 1.f);
    float4 q = nv ? __ldg(pq4 + (size_t)node * 8 + 4 + c)
                  : make_float4(0.f, 0.f, 0.f, 0.f);
    float v[4];
    v[0] = acc.x * invd + q.x;
    v[1] = acc.y * invd + q.y;
    v[2] = acc.z * invd + q.z;
    v[3] = acc.w * invd + q.w;

    float m = fmaxf(fmaxf(v[0], v[1]), fmaxf(v[2], v[3]));
    m = fmaxf(m, __shfl_xor_sync(0xFFFFFFFFu, m, 1));
    m = fmaxf(m, __shfl_xor_sync(0xFFFFFFFFu, m, 2));
    float sum = expf(v[0] - m) + expf(v[1] - m) + expf(v[2] - m) + expf(v[3] - m);
    sum += __shfl_xor_sync(0xFFFFFFFFu, sum, 1);
    sum += __shfl_xor_sync(0xFFFFFFFFu, sum, 2);
    float lse = m + logf(sum);

    if (nv) {
        float4 o;
        o.x = v[0] - lse; o.y = v[1] - lse; o.z = v[2] - lse; o.w = v[3] - lse;
        ((float4*)out)[(size_t)node * 4 + c] = o;
    }
}

// ---------------------------------------------------------------------------
extern "C" void kernel_launch(void* const* d_in, const int* in_sizes, int n_in,
                              void* d_out, int out_size) {
    const float* x   = (const float*)d_in[0];
    const int*   ei  = (const int*)d_in[1];
    const float* W1l = (const float*)d_in[2];
    const float* W1r = (const float*)d_in[3];
    const float* b1  = (const float*)d_in[4];
    const float* W2l = (const float*)d_in[5];
    const float* W2r = (const float*)d_in[6];
    const float* b2  = (const float*)d_in[7];
    float* out = (float*)d_out;

    k_zero_cnt<<<(NN + 1023) / 1024, 1024>>>();
    k_hist<<<(NE + 255) / 256, 256>>>(ei);
    k_scan1<<<196, 512>>>();
    k_scan2<<<1, 256>>>();
    k_scan3<<<(NN + 511) / 512, 512>>>();
    k_fill<<<(NE + 255) / 256, 256>>>(ei);

    static bool attr_set = false;
    if (!attr_set) {
        cudaFuncSetAttribute(mega_kernel,
                             cudaFuncAttributeMaxDynamicSharedMemorySize,
                             SMEM_FLOATS * sizeof(float));
        attr_set = true;
    }
    mega_kernel<<<(NN + 63) / 64, 256, SMEM_FLOATS * sizeof(float)>>>(
        x, W1l, W1r, b1, W2l, W2r, b2);

    final_kernel<<<(NN + 63) / 64, 256>>>(out);
}